// round 14
// baseline (speedup 1.0000x reference)
#include <cuda_runtime.h>
#include <cuda_fp16.h>
#include <math.h>

#define MAXN 50000
#define MAXE 800000
#define C_IN 64
#define C_OUT 64
#define HEADS 4
#define HC 256   // HEADS*C_OUT

// ---------------- scratch (static device globals; no allocation) ----------------
__device__ __half  g_XHH[MAXN * HC];        // 25.6 MB, fp16 gather operand
__device__ float   g_ALS[MAXN * HEADS];
__device__ float   g_ALD[MAXN * HEADS];
__device__ float   g_SAV1[MAXN * C_OUT];
__device__ double  g_BNS[128];
__device__ float   g_SCALE[64];
__device__ float   g_SHIFT[64];
// CSR (built once per launch; structure shared by both layers)
__device__ int     g_DEG[MAXN];
__device__ int     g_ROWPTR[MAXN + 1];
__device__ int     g_CUR[MAXN];
__device__ int     g_CSRC[MAXE + MAXN];
__device__ int     g_CHUNKSUM[64];

// =====================================================================
// CSR build
// =====================================================================
__global__ void deg_init_kernel(int N) {
    int i = blockIdx.x * blockDim.x + threadIdx.x;
    if (i < N) g_DEG[i] = 1;   // self loop
    if (i < 128) g_BNS[i] = 0.0;   // BN stats zero for layer-0
}

__global__ void deg_count_kernel(const int* __restrict__ EDST, int E) {
    int e = blockIdx.x * blockDim.x + threadIdx.x;
    if (e < E) atomicAdd(&g_DEG[EDST[e]], 1);
}

// per-chunk sums (chunk = 1024 nodes)
__global__ void chunk_sum_kernel(int N) {
    __shared__ int sh[32];
    int t = threadIdx.x;
    int i = blockIdx.x * 1024 + t;
    int v = (i < N) ? g_DEG[i] : 0;
#pragma unroll
    for (int o = 16; o > 0; o >>= 1) v += __shfl_xor_sync(0xffffffffu, v, o);
    if ((t & 31) == 0) sh[t >> 5] = v;
    __syncthreads();
    if (t < 32) {
        int x = sh[t];
#pragma unroll
        for (int o = 16; o > 0; o >>= 1) x += __shfl_xor_sync(0xffffffffu, x, o);
        if (t == 0) g_CHUNKSUM[blockIdx.x] = x;
    }
}

// exclusive scan of chunk sums (nchunks <= 64), single block of 64
__global__ void chunk_scan_kernel(int nchunks) {
    __shared__ int sh[64];
    int t = threadIdx.x;
    int v = (t < nchunks) ? g_CHUNKSUM[t] : 0;
    sh[t] = v;
    __syncthreads();
    for (int o = 1; o < 64; o <<= 1) {
        int a = (t >= o) ? sh[t - o] : 0;
        __syncthreads();
        sh[t] += a;
        __syncthreads();
    }
    if (t < nchunks) g_CHUNKSUM[t] = sh[t] - v;   // exclusive
}

// per-chunk exclusive scan + chunk offset -> rowptr, cursor
__global__ void rowptr_kernel(int N) {
    __shared__ int warpsum[32];
    int t = threadIdx.x;
    int i = blockIdx.x * 1024 + t;
    int v = (i < N) ? g_DEG[i] : 0;
    int x = v;
#pragma unroll
    for (int o = 1; o < 32; o <<= 1) {
        int y = __shfl_up_sync(0xffffffffu, x, o);
        if ((t & 31) >= o) x += y;
    }
    if ((t & 31) == 31) warpsum[t >> 5] = x;
    __syncthreads();
    if (t < 32) {
        int y = warpsum[t];
        int z = y;
#pragma unroll
        for (int o = 1; o < 32; o <<= 1) {
            int q = __shfl_up_sync(0xffffffffu, z, o);
            if (t >= o) z += q;
        }
        warpsum[t] = z - y;   // exclusive over warps
    }
    __syncthreads();
    int excl = g_CHUNKSUM[blockIdx.x] + warpsum[t >> 5] + x - v;
    if (i < N) { g_ROWPTR[i] = excl; g_CUR[i] = excl; }
    if (i == N - 1) g_ROWPTR[N] = excl + v;
}

__global__ void fill_kernel(const int* __restrict__ ESRC, const int* __restrict__ EDST,
                            int E, int N) {
    int i = blockIdx.x * blockDim.x + threadIdx.x;
    if (i < E) {
        int dst = EDST[i];
        int pos = atomicAdd(&g_CUR[dst], 1);
        g_CSRC[pos] = ESRC[i];
    } else if (i < E + N) {
        int n = i - E;
        int pos = atomicAdd(&g_CUR[n], 1);
        g_CSRC[pos] = n;
    }
}

// =====================================================================
// GEMM: XH[N,256] = f(X)[N,64] @ W[64,256], fused a_src/a_dst dot epilogue.
// XH stored fp16 (only consumer is the gather). ALS/ALD from fp32 acc.
// f = identity (fuse=0) or relu(scale*x+shift) (fuse=1, layer-1 input BN).
// blockIdx.y == head h (cols [64h, 64h+64)).
// =====================================================================
__global__ void gemm_kernel(const float* __restrict__ X, const float* __restrict__ W,
                            const float* __restrict__ asrc, const float* __restrict__ adst,
                            int N, int fuse) {
    __shared__ float xs[64][65];
    __shared__ float ws[64][65];
    int m0 = blockIdx.x * 64;
    int h = blockIdx.y;
    int j0 = h * 64;
    int tid = threadIdx.x;
    for (int i = tid; i < 64 * 64; i += 256) {
        int r = i >> 6, k = i & 63;
        int row = m0 + r;
        float v = (row < N) ? X[row * 64 + k] : 0.0f;
        if (fuse) {
            v = g_SCALE[k] * v + g_SHIFT[k];
            v = v > 0.0f ? v : 0.0f;
        }
        xs[r][k] = v;
        ws[r][k] = W[r * HC + j0 + k];   // ws[k][j]
    }
    __syncthreads();
    int tx = tid & 15, ty = tid >> 4;
    float acc[4][4];
#pragma unroll
    for (int i = 0; i < 4; i++)
#pragma unroll
        for (int j = 0; j < 4; j++) acc[i][j] = 0.0f;
#pragma unroll 8
    for (int k = 0; k < 64; k++) {
        float a[4], b[4];
#pragma unroll
        for (int i = 0; i < 4; i++) a[i] = xs[ty * 4 + i][k];
#pragma unroll
        for (int j = 0; j < 4; j++) b[j] = ws[k][tx * 4 + j];
#pragma unroll
        for (int i = 0; i < 4; i++)
#pragma unroll
            for (int j = 0; j < 4; j++) acc[i][j] += a[i] * b[j];
    }
    // store XH as fp16 (4 halfs = one 8B vector store per row-slice)
#pragma unroll
    for (int i = 0; i < 4; i++) {
        int row = m0 + ty * 4 + i;
        if (row < N) {
            __half2 h0 = __floats2half2_rn(acc[i][0], acc[i][1]);
            __half2 h1 = __floats2half2_rn(acc[i][2], acc[i][3]);
            uint2 pk;
            pk.x = *(unsigned int*)&h0;
            pk.y = *(unsigned int*)&h1;
            *(uint2*)(g_XHH + (size_t)row * HC + j0 + tx * 4) = pk;
        }
    }
    // fused epilogue: als/ald = dot(acc_row, asrc/adst[h])  (fp32, pre-quantization)
    float a_s[4], a_d[4];
#pragma unroll
    for (int j = 0; j < 4; j++) {
        a_s[j] = asrc[j0 + tx * 4 + j];
        a_d[j] = adst[j0 + tx * 4 + j];
    }
#pragma unroll
    for (int i = 0; i < 4; i++) {
        float ss = 0.0f, sd = 0.0f;
#pragma unroll
        for (int j = 0; j < 4; j++) {
            ss += acc[i][j] * a_s[j];
            sd += acc[i][j] * a_d[j];
        }
#pragma unroll
        for (int o = 8; o > 0; o >>= 1) {
            ss += __shfl_xor_sync(0xffffffffu, ss, o);
            sd += __shfl_xor_sync(0xffffffffu, sd, o);
        }
        int row = m0 + ty * 4 + i;
        if (tx == 0 && row < N) {
            g_ALS[row * 4 + h] = ss;
            g_ALD[row * 4 + h] = sd;
        }
    }
}

// =====================================================================
// GAT aggregation, warp-split for MLP. One 64-thread block per node.
// Warp w owns edges {i : i mod 2 == w} — fully independent until the end.
// Lane l owns halfs [8l, 8l+8) of the 256-half row: head hh=l>>3,
// channels (l&7)*8..+8 within the head. Gather = one 16B LDG per edge,
// unrolled x4 for 4 outstanding loads. No atomics, no edge buffer,
// no segment-max (softmax is shift-invariant).
// =====================================================================
__global__ __launch_bounds__(64) void gat_aggregate_kernel(
        const float* __restrict__ bias, float* __restrict__ SAV, int N) {
    int n = blockIdx.x;
    int t = threadIdx.x;
    int lane = t & 31, w = t >> 5;
    int base = g_ROWPTR[n];
    int deg  = g_ROWPTR[n + 1] - base;
    int hh = lane >> 3;              // head of this lane
    int coff = lane * 8;             // half-offset within row (16B aligned)

    __shared__ int    ssh[2][32];
    __shared__ float  psh[2][4][36];
    __shared__ float4 shp[2];
    __shared__ float  osh[64];

    float4 ald = *(const float4*)(g_ALD + n * 4);
    const int* __restrict__ csrc = g_CSRC + base;

    float acc[8];
#pragma unroll
    for (int j = 0; j < 8; j++) acc[j] = 0.0f;
    float4 psum = make_float4(0.0f, 0.0f, 0.0f, 0.0f);

    int cw = (deg - w + 1) >> 1;     // #edges with index ≡ w (mod 2)

    for (int kb = 0; kb < cw; kb += 32) {
        int kcnt = min(32, cw - kb);
        if (lane < kcnt) {
            int s = csrc[2 * (kb + lane) + w];
            ssh[w][lane] = s;
            float4 a = *(const float4*)(g_ALS + s * 4);
            float e0 = a.x + ald.x; e0 = e0 > 0.0f ? e0 : 0.2f * e0;
            float e1 = a.y + ald.y; e1 = e1 > 0.0f ? e1 : 0.2f * e1;
            float e2 = a.z + ald.z; e2 = e2 > 0.0f ? e2 : 0.2f * e2;
            float e3 = a.w + ald.w; e3 = e3 > 0.0f ? e3 : 0.2f * e3;
            float p0 = __expf(e0); psh[w][0][lane] = p0; psum.x += p0;
            float p1 = __expf(e1); psh[w][1][lane] = p1; psum.y += p1;
            float p2 = __expf(e2); psh[w][2][lane] = p2; psum.z += p2;
            float p3 = __expf(e3); psh[w][3][lane] = p3; psum.w += p3;
        }
        __syncwarp();
        int k = 0;
        for (; k + 4 <= kcnt; k += 4) {
            int s0 = ssh[w][k],     s1 = ssh[w][k + 1];
            int s2 = ssh[w][k + 2], s3 = ssh[w][k + 3];
            float ph0 = psh[w][hh][k],     ph1 = psh[w][hh][k + 1];
            float ph2 = psh[w][hh][k + 2], ph3 = psh[w][hh][k + 3];
            float4 v0 = *(const float4*)(g_XHH + (size_t)s0 * HC + coff);
            float4 v1 = *(const float4*)(g_XHH + (size_t)s1 * HC + coff);
            float4 v2 = *(const float4*)(g_XHH + (size_t)s2 * HC + coff);
            float4 v3 = *(const float4*)(g_XHH + (size_t)s3 * HC + coff);
            const __half2* h0 = (const __half2*)&v0;
            const __half2* h1 = (const __half2*)&v1;
            const __half2* h2 = (const __half2*)&v2;
            const __half2* h3 = (const __half2*)&v3;
#pragma unroll
            for (int q = 0; q < 4; q++) {
                float2 f0 = __half22float2(h0[q]);
                float2 f1 = __half22float2(h1[q]);
                float2 f2 = __half22float2(h2[q]);
                float2 f3 = __half22float2(h3[q]);
                acc[2 * q]     += ph0 * f0.x + ph1 * f1.x + ph2 * f2.x + ph3 * f3.x;
                acc[2 * q + 1] += ph0 * f0.y + ph1 * f1.y + ph2 * f2.y + ph3 * f3.y;
            }
        }
        for (; k < kcnt; k++) {
            int s0 = ssh[w][k];
            float ph0 = psh[w][hh][k];
            float4 v0 = *(const float4*)(g_XHH + (size_t)s0 * HC + coff);
            const __half2* h0 = (const __half2*)&v0;
#pragma unroll
            for (int q = 0; q < 4; q++) {
                float2 f0 = __half22float2(h0[q]);
                acc[2 * q]     += ph0 * f0.x;
                acc[2 * q + 1] += ph0 * f0.y;
            }
        }
        __syncwarp();
    }

    // per-warp psum reduce -> smem
#pragma unroll
    for (int o = 16; o > 0; o >>= 1) {
        psum.x += __shfl_xor_sync(0xffffffffu, psum.x, o);
        psum.y += __shfl_xor_sync(0xffffffffu, psum.y, o);
        psum.z += __shfl_xor_sync(0xffffffffu, psum.z, o);
        psum.w += __shfl_xor_sync(0xffffffffu, psum.w, o);
    }
    if (lane == 0) shp[w] = psum;
    __syncthreads();
    float4 pa = shp[0], pb = shp[1];
    float pt0 = pa.x + pb.x, pt1 = pa.y + pb.y, pt2 = pa.z + pb.z, pt3 = pa.w + pb.w;
    float psum_h = (hh == 0) ? pt0 : (hh == 1) ? pt1 : (hh == 2) ? pt2 : pt3;
    float rc = 0.25f / (psum_h + 1e-16f);

    // scale, then in-warp head reduction: xor8 and xor16 pair same-channel lanes
#pragma unroll
    for (int j = 0; j < 8; j++) {
        acc[j] *= rc;
        acc[j] += __shfl_xor_sync(0xffffffffu, acc[j], 8);
        acc[j] += __shfl_xor_sync(0xffffffffu, acc[j], 16);
    }
    // lanes 0..7 now hold channels lane*8..+8 summed over heads (for this warp's edges)
    if (w == 1 && lane < 8) {
#pragma unroll
        for (int j = 0; j < 8; j++) osh[lane * 8 + j] = acc[j];
    }
    __syncthreads();
    if (w == 0 && lane < 8) {
        float* dst = SAV + (size_t)n * 64 + lane * 8;
        const float* bi = bias + lane * 8;
#pragma unroll
        for (int j = 0; j < 8; j++)
            dst[j] = acc[j] + osh[lane * 8 + j] + bi[j];
    }
}

// =====================================================================
// BatchNorm
// =====================================================================
__global__ void stats_kernel(const float* __restrict__ SAV, int N) {
    __shared__ float s1[64], s2[64];
    if (threadIdx.x < 64) { s1[threadIdx.x] = 0.0f; s2[threadIdx.x] = 0.0f; }
    __syncthreads();
    int c = threadIdx.x & 63;
    float ls = 0.0f, lq = 0.0f;
    int total = N * 64;
    int stride = gridDim.x * blockDim.x;   // multiple of 64
    for (int i = blockIdx.x * blockDim.x + threadIdx.x; i < total; i += stride) {
        float v = SAV[i];
        ls += v;
        lq += v * v;
    }
    atomicAdd(&s1[c], ls);
    atomicAdd(&s2[c], lq);
    __syncthreads();
    if (threadIdx.x < 64) {
        atomicAdd(&g_BNS[threadIdx.x], (double)s1[threadIdx.x]);
        atomicAdd(&g_BNS[64 + threadIdx.x], (double)s2[threadIdx.x]);
    }
}

// reads BNS -> SCALE/SHIFT, then zeroes BNS for the next stats pass
__global__ void bn_param_kernel(const float* __restrict__ gamma, const float* __restrict__ beta, int N) {
    int c = threadIdx.x;
    if (c >= 64) return;
    double mean = g_BNS[c] / (double)N;
    double var = g_BNS[64 + c] / (double)N - mean * mean;
    float sc = gamma[c] * rsqrtf((float)(var + 1e-5));
    g_SCALE[c] = sc;
    g_SHIFT[c] = beta[c] - (float)mean * sc;
    g_BNS[c] = 0.0;
    g_BNS[64 + c] = 0.0;
}

__global__ void bn_relu_kernel(const float* __restrict__ SAV, float* __restrict__ OUT, int N) {
    int i = blockIdx.x * blockDim.x + threadIdx.x;
    if (i >= N * 64) return;
    int c = i & 63;
    float v = g_SCALE[c] * SAV[i] + g_SHIFT[c];
    OUT[i] = v > 0.0f ? v : 0.0f;
}

// =====================================================================
// host launch
// =====================================================================
extern "C" void kernel_launch(void* const* d_in, const int* in_sizes, int n_in,
                              void* d_out, int out_size) {
    const float* x  = (const float*)d_in[0];
    const int*   EI = (const int*)d_in[1];   // int32 node ids
    // d_in[2] = edge_weight (ignored, edge_dim=None)
    const float* W0 = (const float*)d_in[3];
    const float* as0 = (const float*)d_in[4];
    const float* ad0 = (const float*)d_in[5];
    const float* b0 = (const float*)d_in[6];
    const float* g0 = (const float*)d_in[7];
    const float* be0 = (const float*)d_in[8];
    const float* W1 = (const float*)d_in[9];
    const float* as1 = (const float*)d_in[10];
    const float* ad1 = (const float*)d_in[11];
    const float* b1 = (const float*)d_in[12];
    const float* g1 = (const float*)d_in[13];
    const float* be1 = (const float*)d_in[14];

    int N = in_sizes[0] / C_IN;
    int E = in_sizes[1] / 2;
    if (N > MAXN) N = MAXN;
    if (E > MAXE) E = MAXE;

    const int* ESRC = EI;        // edge_index[0]
    const int* EDST = EI + E;    // edge_index[1]

    float* out = (float*)d_out;           // [0 : N*64)        -> x (post bn+relu)
    float* saved = out + (size_t)N * 64;  // [N*64 : 2*N*64)   -> layer-2 pre-BN

    float* dSAV1;
    cudaGetSymbolAddress((void**)&dSAV1, g_SAV1);

    int nchunks = (N + 1023) / 1024;

    // ---- CSR build (structure shared by both layers) ----
    deg_init_kernel<<<(N + 255) / 256, 256>>>(N);
    deg_count_kernel<<<(E + 255) / 256, 256>>>(EDST, E);
    chunk_sum_kernel<<<nchunks, 1024>>>(N);
    chunk_scan_kernel<<<1, 64>>>(nchunks);
    rowptr_kernel<<<nchunks, 1024>>>(N);
    fill_kernel<<<(E + N + 255) / 256, 256>>>(ESRC, EDST, E, N);

    dim3 gg((N + 63) / 64, HEADS);

    // ---- layer 0 ----
    gemm_kernel<<<gg, 256>>>(x, W0, as0, ad0, N, 0);
    gat_aggregate_kernel<<<N, 64>>>(b0, dSAV1, N);
    stats_kernel<<<1024, 256>>>(dSAV1, N);
    bn_param_kernel<<<1, 64>>>(g0, be0, N);   // -> SCALE/SHIFT; zeroes BNS

    // ---- layer 1 (BN+ReLU of layer-0 fused into the GEMM x-loader) ----
    gemm_kernel<<<gg, 256>>>(dSAV1, W1, as1, ad1, N, 1);
    gat_aggregate_kernel<<<N, 64>>>(b1, saved, N);   // pre-BN straight to d_out
    stats_kernel<<<1024, 256>>>(saved, N);
    bn_param_kernel<<<1, 64>>>(g1, be1, N);
    bn_relu_kernel<<<(N * 64 + 255) / 256, 256>>>(saved, out, N);
}

// round 15
// speedup vs baseline: 1.0887x; 1.0887x over previous
#include <cuda_runtime.h>
#include <cuda_fp16.h>
#include <math.h>

#define MAXN 50000
#define MAXE 800000
#define C_IN 64
#define C_OUT 64
#define HEADS 4
#define HC 256   // HEADS*C_OUT
#define AGG_WARPS 8

// ---------------- scratch (static device globals; no allocation) ----------------
__device__ __half  g_XHH[MAXN * HC];        // 25.6 MB, fp16 gather operand
__device__ float   g_ALS[MAXN * HEADS];
__device__ float   g_ALD[MAXN * HEADS];
__device__ float   g_SAV1[MAXN * C_OUT];
__device__ double  g_BNS[128];
__device__ float   g_SCALE[64];
__device__ float   g_SHIFT[64];
// CSR (built once per launch; structure shared by both layers)
__device__ int     g_DEG[MAXN];
__device__ int     g_ROWPTR[MAXN + 1];
__device__ int     g_CUR[MAXN];
__device__ int     g_CSRC[MAXE + MAXN];
__device__ int     g_CHUNKSUM[64];

// =====================================================================
// CSR build
// =====================================================================
__global__ void deg_init_kernel(int N) {
    int i = blockIdx.x * blockDim.x + threadIdx.x;
    if (i < N) g_DEG[i] = 1;   // self loop
    if (i < 128) g_BNS[i] = 0.0;   // BN stats zero for layer-0
}

__global__ void deg_count_kernel(const int* __restrict__ EDST, int E) {
    int e = blockIdx.x * blockDim.x + threadIdx.x;
    if (e < E) atomicAdd(&g_DEG[EDST[e]], 1);
}

// per-chunk sums (chunk = 1024 nodes)
__global__ void chunk_sum_kernel(int N) {
    __shared__ int sh[32];
    int t = threadIdx.x;
    int i = blockIdx.x * 1024 + t;
    int v = (i < N) ? g_DEG[i] : 0;
#pragma unroll
    for (int o = 16; o > 0; o >>= 1) v += __shfl_xor_sync(0xffffffffu, v, o);
    if ((t & 31) == 0) sh[t >> 5] = v;
    __syncthreads();
    if (t < 32) {
        int x = sh[t];
#pragma unroll
        for (int o = 16; o > 0; o >>= 1) x += __shfl_xor_sync(0xffffffffu, x, o);
        if (t == 0) g_CHUNKSUM[blockIdx.x] = x;
    }
}

// exclusive scan of chunk sums (nchunks <= 64), single block of 64
__global__ void chunk_scan_kernel(int nchunks) {
    __shared__ int sh[64];
    int t = threadIdx.x;
    int v = (t < nchunks) ? g_CHUNKSUM[t] : 0;
    sh[t] = v;
    __syncthreads();
    for (int o = 1; o < 64; o <<= 1) {
        int a = (t >= o) ? sh[t - o] : 0;
        __syncthreads();
        sh[t] += a;
        __syncthreads();
    }
    if (t < nchunks) g_CHUNKSUM[t] = sh[t] - v;   // exclusive
}

// per-chunk exclusive scan + chunk offset -> rowptr, cursor
__global__ void rowptr_kernel(int N) {
    __shared__ int warpsum[32];
    int t = threadIdx.x;
    int i = blockIdx.x * 1024 + t;
    int v = (i < N) ? g_DEG[i] : 0;
    int x = v;
#pragma unroll
    for (int o = 1; o < 32; o <<= 1) {
        int y = __shfl_up_sync(0xffffffffu, x, o);
        if ((t & 31) >= o) x += y;
    }
    if ((t & 31) == 31) warpsum[t >> 5] = x;
    __syncthreads();
    if (t < 32) {
        int y = warpsum[t];
        int z = y;
#pragma unroll
        for (int o = 1; o < 32; o <<= 1) {
            int q = __shfl_up_sync(0xffffffffu, z, o);
            if (t >= o) z += q;
        }
        warpsum[t] = z - y;   // exclusive over warps
    }
    __syncthreads();
    int excl = g_CHUNKSUM[blockIdx.x] + warpsum[t >> 5] + x - v;
    if (i < N) { g_ROWPTR[i] = excl; g_CUR[i] = excl; }
    if (i == N - 1) g_ROWPTR[N] = excl + v;
}

__global__ void fill_kernel(const int* __restrict__ ESRC, const int* __restrict__ EDST,
                            int E, int N) {
    int i = blockIdx.x * blockDim.x + threadIdx.x;
    if (i < E) {
        int dst = EDST[i];
        int pos = atomicAdd(&g_CUR[dst], 1);
        g_CSRC[pos] = ESRC[i];
    } else if (i < E + N) {
        int n = i - E;
        int pos = atomicAdd(&g_CUR[n], 1);
        g_CSRC[pos] = n;
    }
}

// =====================================================================
// GEMM: XH[N,256] = f(X)[N,64] @ W[64,256], fused a_src/a_dst dot epilogue.
// XH stored fp16 (only consumer is the gather). ALS/ALD from fp32 acc.
// f = identity (fuse=0) or relu(scale*x+shift) (fuse=1, layer-1 input BN).
// blockIdx.y == head h (cols [64h, 64h+64)).
// =====================================================================
__global__ void gemm_kernel(const float* __restrict__ X, const float* __restrict__ W,
                            const float* __restrict__ asrc, const float* __restrict__ adst,
                            int N, int fuse) {
    __shared__ float xs[64][65];
    __shared__ float ws[64][65];
    int m0 = blockIdx.x * 64;
    int h = blockIdx.y;
    int j0 = h * 64;
    int tid = threadIdx.x;
    for (int i = tid; i < 64 * 64; i += 256) {
        int r = i >> 6, k = i & 63;
        int row = m0 + r;
        float v = (row < N) ? X[row * 64 + k] : 0.0f;
        if (fuse) {
            v = g_SCALE[k] * v + g_SHIFT[k];
            v = v > 0.0f ? v : 0.0f;
        }
        xs[r][k] = v;
        ws[r][k] = W[r * HC + j0 + k];   // ws[k][j]
    }
    __syncthreads();
    int tx = tid & 15, ty = tid >> 4;
    float acc[4][4];
#pragma unroll
    for (int i = 0; i < 4; i++)
#pragma unroll
        for (int j = 0; j < 4; j++) acc[i][j] = 0.0f;
#pragma unroll 8
    for (int k = 0; k < 64; k++) {
        float a[4], b[4];
#pragma unroll
        for (int i = 0; i < 4; i++) a[i] = xs[ty * 4 + i][k];
#pragma unroll
        for (int j = 0; j < 4; j++) b[j] = ws[k][tx * 4 + j];
#pragma unroll
        for (int i = 0; i < 4; i++)
#pragma unroll
            for (int j = 0; j < 4; j++) acc[i][j] += a[i] * b[j];
    }
    // store XH as fp16 (4 halfs = one 8B vector store per row-slice)
#pragma unroll
    for (int i = 0; i < 4; i++) {
        int row = m0 + ty * 4 + i;
        if (row < N) {
            __half2 h0 = __floats2half2_rn(acc[i][0], acc[i][1]);
            __half2 h1 = __floats2half2_rn(acc[i][2], acc[i][3]);
            uint2 pk;
            pk.x = *(unsigned int*)&h0;
            pk.y = *(unsigned int*)&h1;
            *(uint2*)(g_XHH + (size_t)row * HC + j0 + tx * 4) = pk;
        }
    }
    // fused epilogue: als/ald = dot(acc_row, asrc/adst[h])  (fp32, pre-quantization)
    float a_s[4], a_d[4];
#pragma unroll
    for (int j = 0; j < 4; j++) {
        a_s[j] = asrc[j0 + tx * 4 + j];
        a_d[j] = adst[j0 + tx * 4 + j];
    }
#pragma unroll
    for (int i = 0; i < 4; i++) {
        float ss = 0.0f, sd = 0.0f;
#pragma unroll
        for (int j = 0; j < 4; j++) {
            ss += acc[i][j] * a_s[j];
            sd += acc[i][j] * a_d[j];
        }
#pragma unroll
        for (int o = 8; o > 0; o >>= 1) {
            ss += __shfl_xor_sync(0xffffffffu, ss, o);
            sd += __shfl_xor_sync(0xffffffffu, sd, o);
        }
        int row = m0 + ty * 4 + i;
        if (tx == 0 && row < N) {
            g_ALS[row * 4 + h] = ss;
            g_ALD[row * 4 + h] = sd;
        }
    }
}

// =====================================================================
// GAT aggregation: ONE WARP per node. Lane l owns halfs [8l, 8l+8) of the
// 256-half row (head hh=l>>3, channels (l&7)*8..+8) — one 16B LDG per edge
// per lane, unrolled x4 for MLP. No block syncs, no atomics, no edge
// buffer, no segment-max (softmax is shift-invariant). psum via full shfl
// butterfly; head reduction via shfl_xor 8/16; lanes 0-7 store the row.
// =====================================================================
__global__ __launch_bounds__(32 * AGG_WARPS) void gat_aggregate_kernel(
        const float* __restrict__ bias, float* __restrict__ SAV, int N) {
    int wid  = threadIdx.x >> 5;
    int lane = threadIdx.x & 31;
    int n = blockIdx.x * AGG_WARPS + wid;
    if (n >= N) return;

    __shared__ int   ssh[AGG_WARPS][32];
    __shared__ float psh[AGG_WARPS][4][33];

    int base = g_ROWPTR[n];
    int deg  = g_ROWPTR[n + 1] - base;
    int hh   = lane >> 3;            // head of this lane
    int coff = lane * 8;             // half-offset within row (16B aligned)

    float4 ald = *(const float4*)(g_ALD + n * 4);
    const int* __restrict__ csrc = g_CSRC + base;

    float acc[8];
#pragma unroll
    for (int j = 0; j < 8; j++) acc[j] = 0.0f;
    float4 psum = make_float4(0.0f, 0.0f, 0.0f, 0.0f);

    for (int tb = 0; tb < deg; tb += 32) {
        int cnt = min(32, deg - tb);
        if (lane < cnt) {
            int s = csrc[tb + lane];                 // coalesced
            ssh[wid][lane] = s;
            float4 a = *(const float4*)(g_ALS + s * 4);
            float e0 = a.x + ald.x; e0 = e0 > 0.0f ? e0 : 0.2f * e0;
            float e1 = a.y + ald.y; e1 = e1 > 0.0f ? e1 : 0.2f * e1;
            float e2 = a.z + ald.z; e2 = e2 > 0.0f ? e2 : 0.2f * e2;
            float e3 = a.w + ald.w; e3 = e3 > 0.0f ? e3 : 0.2f * e3;
            float p0 = __expf(e0); psh[wid][0][lane] = p0; psum.x += p0;
            float p1 = __expf(e1); psh[wid][1][lane] = p1; psum.y += p1;
            float p2 = __expf(e2); psh[wid][2][lane] = p2; psum.z += p2;
            float p3 = __expf(e3); psh[wid][3][lane] = p3; psum.w += p3;
        }
        __syncwarp();
        int k = 0;
        for (; k + 4 <= cnt; k += 4) {
            int s0 = ssh[wid][k],     s1 = ssh[wid][k + 1];
            int s2 = ssh[wid][k + 2], s3 = ssh[wid][k + 3];
            float ph0 = psh[wid][hh][k],     ph1 = psh[wid][hh][k + 1];
            float ph2 = psh[wid][hh][k + 2], ph3 = psh[wid][hh][k + 3];
            float4 v0 = *(const float4*)(g_XHH + (size_t)s0 * HC + coff);
            float4 v1 = *(const float4*)(g_XHH + (size_t)s1 * HC + coff);
            float4 v2 = *(const float4*)(g_XHH + (size_t)s2 * HC + coff);
            float4 v3 = *(const float4*)(g_XHH + (size_t)s3 * HC + coff);
            const __half2* h0 = (const __half2*)&v0;
            const __half2* h1 = (const __half2*)&v1;
            const __half2* h2 = (const __half2*)&v2;
            const __half2* h3 = (const __half2*)&v3;
#pragma unroll
            for (int q = 0; q < 4; q++) {
                float2 f0 = __half22float2(h0[q]);
                float2 f1 = __half22float2(h1[q]);
                float2 f2 = __half22float2(h2[q]);
                float2 f3 = __half22float2(h3[q]);
                acc[2 * q]     += ph0 * f0.x + ph1 * f1.x + ph2 * f2.x + ph3 * f3.x;
                acc[2 * q + 1] += ph0 * f0.y + ph1 * f1.y + ph2 * f2.y + ph3 * f3.y;
            }
        }
        for (; k < cnt; k++) {
            int s0 = ssh[wid][k];
            float ph0 = psh[wid][hh][k];
            float4 v0 = *(const float4*)(g_XHH + (size_t)s0 * HC + coff);
            const __half2* h0 = (const __half2*)&v0;
#pragma unroll
            for (int q = 0; q < 4; q++) {
                float2 f0 = __half22float2(h0[q]);
                acc[2 * q]     += ph0 * f0.x;
                acc[2 * q + 1] += ph0 * f0.y;
            }
        }
        __syncwarp();
    }

    // psum butterfly: every lane ends with all four head totals
#pragma unroll
    for (int o = 16; o > 0; o >>= 1) {
        psum.x += __shfl_xor_sync(0xffffffffu, psum.x, o);
        psum.y += __shfl_xor_sync(0xffffffffu, psum.y, o);
        psum.z += __shfl_xor_sync(0xffffffffu, psum.z, o);
        psum.w += __shfl_xor_sync(0xffffffffu, psum.w, o);
    }
    float psum_h = (hh == 0) ? psum.x : (hh == 1) ? psum.y : (hh == 2) ? psum.z : psum.w;
    float rc = 0.25f / (psum_h + 1e-16f);

    // scale, then head reduction: lanes {l, l^8, l^16, l^24} hold the same
    // channel group across the 4 heads — xor8 + xor16 sums them.
#pragma unroll
    for (int j = 0; j < 8; j++) {
        acc[j] *= rc;
        acc[j] += __shfl_xor_sync(0xffffffffu, acc[j], 8);
        acc[j] += __shfl_xor_sync(0xffffffffu, acc[j], 16);
    }
    if (lane < 8) {
        float* dst = SAV + (size_t)n * 64 + lane * 8;
        const float* bi = bias + lane * 8;
#pragma unroll
        for (int j = 0; j < 8; j++)
            dst[j] = acc[j] + bi[j];
    }
}

// =====================================================================
// BatchNorm
// =====================================================================
__global__ void stats_kernel(const float* __restrict__ SAV, int N) {
    __shared__ float s1[64], s2[64];
    if (threadIdx.x < 64) { s1[threadIdx.x] = 0.0f; s2[threadIdx.x] = 0.0f; }
    __syncthreads();
    int c = threadIdx.x & 63;
    float ls = 0.0f, lq = 0.0f;
    int total = N * 64;
    int stride = gridDim.x * blockDim.x;   // multiple of 64
    for (int i = blockIdx.x * blockDim.x + threadIdx.x; i < total; i += stride) {
        float v = SAV[i];
        ls += v;
        lq += v * v;
    }
    atomicAdd(&s1[c], ls);
    atomicAdd(&s2[c], lq);
    __syncthreads();
    if (threadIdx.x < 64) {
        atomicAdd(&g_BNS[threadIdx.x], (double)s1[threadIdx.x]);
        atomicAdd(&g_BNS[64 + threadIdx.x], (double)s2[threadIdx.x]);
    }
}

// reads BNS -> SCALE/SHIFT, then zeroes BNS for the next stats pass
__global__ void bn_param_kernel(const float* __restrict__ gamma, const float* __restrict__ beta, int N) {
    int c = threadIdx.x;
    if (c >= 64) return;
    double mean = g_BNS[c] / (double)N;
    double var = g_BNS[64 + c] / (double)N - mean * mean;
    float sc = gamma[c] * rsqrtf((float)(var + 1e-5));
    g_SCALE[c] = sc;
    g_SHIFT[c] = beta[c] - (float)mean * sc;
    g_BNS[c] = 0.0;
    g_BNS[64 + c] = 0.0;
}

__global__ void bn_relu_kernel(const float* __restrict__ SAV, float* __restrict__ OUT, int N) {
    int i = blockIdx.x * blockDim.x + threadIdx.x;
    if (i >= N * 64) return;
    int c = i & 63;
    float v = g_SCALE[c] * SAV[i] + g_SHIFT[c];
    OUT[i] = v > 0.0f ? v : 0.0f;
}

// =====================================================================
// host launch
// =====================================================================
extern "C" void kernel_launch(void* const* d_in, const int* in_sizes, int n_in,
                              void* d_out, int out_size) {
    const float* x  = (const float*)d_in[0];
    const int*   EI = (const int*)d_in[1];   // int32 node ids
    // d_in[2] = edge_weight (ignored, edge_dim=None)
    const float* W0 = (const float*)d_in[3];
    const float* as0 = (const float*)d_in[4];
    const float* ad0 = (const float*)d_in[5];
    const float* b0 = (const float*)d_in[6];
    const float* g0 = (const float*)d_in[7];
    const float* be0 = (const float*)d_in[8];
    const float* W1 = (const float*)d_in[9];
    const float* as1 = (const float*)d_in[10];
    const float* ad1 = (const float*)d_in[11];
    const float* b1 = (const float*)d_in[12];
    const float* g1 = (const float*)d_in[13];
    const float* be1 = (const float*)d_in[14];

    int N = in_sizes[0] / C_IN;
    int E = in_sizes[1] / 2;
    if (N > MAXN) N = MAXN;
    if (E > MAXE) E = MAXE;

    const int* ESRC = EI;        // edge_index[0]
    const int* EDST = EI + E;    // edge_index[1]

    float* out = (float*)d_out;           // [0 : N*64)        -> x (post bn+relu)
    float* saved = out + (size_t)N * 64;  // [N*64 : 2*N*64)   -> layer-2 pre-BN

    float* dSAV1;
    cudaGetSymbolAddress((void**)&dSAV1, g_SAV1);

    int nchunks = (N + 1023) / 1024;

    // ---- CSR build (structure shared by both layers) ----
    deg_init_kernel<<<(N + 255) / 256, 256>>>(N);
    deg_count_kernel<<<(E + 255) / 256, 256>>>(EDST, E);
    chunk_sum_kernel<<<nchunks, 1024>>>(N);
    chunk_scan_kernel<<<1, 64>>>(nchunks);
    rowptr_kernel<<<nchunks, 1024>>>(N);
    fill_kernel<<<(E + N + 255) / 256, 256>>>(ESRC, EDST, E, N);

    dim3 gg((N + 63) / 64, HEADS);
    int agg_blocks = (N + AGG_WARPS - 1) / AGG_WARPS;

    // ---- layer 0 ----
    gemm_kernel<<<gg, 256>>>(x, W0, as0, ad0, N, 0);
    gat_aggregate_kernel<<<agg_blocks, 32 * AGG_WARPS>>>(b0, dSAV1, N);
    stats_kernel<<<1024, 256>>>(dSAV1, N);
    bn_param_kernel<<<1, 64>>>(g0, be0, N);   // -> SCALE/SHIFT; zeroes BNS

    // ---- layer 1 (BN+ReLU of layer-0 fused into the GEMM x-loader) ----
    gemm_kernel<<<gg, 256>>>(dSAV1, W1, as1, ad1, N, 1);
    gat_aggregate_kernel<<<agg_blocks, 32 * AGG_WARPS>>>(b1, saved, N);   // pre-BN straight to d_out
    stats_kernel<<<1024, 256>>>(saved, N);
    bn_param_kernel<<<1, 64>>>(g1, be1, N);
    bn_relu_kernel<<<(N * 64 + 255) / 256, 256>>>(saved, out, N);
}